// round 2
// baseline (speedup 1.0000x reference)
#include <cuda_runtime.h>
#include <cuda_bf16.h>
#include <cooperative_groups.h>

namespace cg = cooperative_groups;

// Problem constants
#define BB 128          // batch
#define SS 1024         // seq
#define II 768          // input dim
#define HH 256          // hidden
#define OO 6            // output
#define MM (BB * SS)    // 131072 rows
#define G3 (3 * HH)     // 768 gate rows

// ---------------------------------------------------------------------------
// Scratch (device globals — allocation-free rule)
// ---------------------------------------------------------------------------
__device__ float g_xg[(size_t)MM * G3];   // [M, 768]  x @ W_ih^T + b_ih
__device__ float g_hs[(size_t)MM * HH];   // [M, 256]  hidden states

typedef unsigned long long ull;

// ===========================================================================
// Kernel 1: xg = x @ W_ih^T + b_ih      (A[M,K] * B[N,K]^T, K=768, N=768)
// Tiles: BM=128, BN=128, BK=16. 256 threads, 8x8 per thread, FFMA2 inner.
// ===========================================================================
__global__ __launch_bounds__(256) void gemm_xg_kernel(
    const float* __restrict__ x, const float* __restrict__ W,
    const float* __restrict__ bias)
{
    __shared__ __align__(16) float As[16][132];
    __shared__ __align__(16) float Bs[16][132];

    const int tid  = threadIdx.x;
    const int nblk = blockIdx.x;          // 0..5
    const size_t mblk = blockIdx.y;       // 0..1023

    const float* Aptr = x + mblk * 128 * II;
    const float* Bptr = W + (size_t)nblk * 128 * II;

    const int tm = tid >> 4;              // 0..15
    const int tn = tid & 15;              // 0..15

    ull acc[8][4];
#pragma unroll
    for (int i = 0; i < 8; i++)
#pragma unroll
        for (int j = 0; j < 4; j++) acc[i][j] = 0ull;

    for (int k0 = 0; k0 < II; k0 += 16) {
#pragma unroll
        for (int i = 0; i < 2; i++) {
            int idx = tid + i * 256;      // 0..511
            int row = idx >> 2;           // 0..127
            int c4  = idx & 3;            // 0..3
            float4 av = __ldg((const float4*)(Aptr + (size_t)row * II + k0 + c4 * 4));
            As[c4 * 4 + 0][row] = av.x;
            As[c4 * 4 + 1][row] = av.y;
            As[c4 * 4 + 2][row] = av.z;
            As[c4 * 4 + 3][row] = av.w;
            float4 bv = __ldg((const float4*)(Bptr + (size_t)row * II + k0 + c4 * 4));
            Bs[c4 * 4 + 0][row] = bv.x;
            Bs[c4 * 4 + 1][row] = bv.y;
            Bs[c4 * 4 + 2][row] = bv.z;
            Bs[c4 * 4 + 3][row] = bv.w;
        }
        __syncthreads();

#pragma unroll
        for (int k = 0; k < 16; k++) {
            float a[8];
            *(float4*)(a)     = *(const float4*)&As[k][tm * 8];
            *(float4*)(a + 4) = *(const float4*)&As[k][tm * 8 + 4];
            ull b2[4];
            {
                ulonglong2 t0 = *(const ulonglong2*)&Bs[k][tn * 8];
                ulonglong2 t1 = *(const ulonglong2*)&Bs[k][tn * 8 + 4];
                b2[0] = t0.x; b2[1] = t0.y; b2[2] = t1.x; b2[3] = t1.y;
            }
#pragma unroll
            for (int i = 0; i < 8; i++) {
                ull ad;
                asm("mov.b64 %0, {%1, %1};" : "=l"(ad) : "f"(a[i]));
#pragma unroll
                for (int j = 0; j < 4; j++)
                    asm("fma.rn.f32x2 %0, %1, %2, %0;"
                        : "+l"(acc[i][j]) : "l"(ad), "l"(b2[j]));
            }
        }
        __syncthreads();
    }

    // Epilogue: add bias, store 8x8
    const int n_base = nblk * 128 + tn * 8;
    float bl[8];
    *(float4*)(bl)     = __ldg((const float4*)(bias + n_base));
    *(float4*)(bl + 4) = __ldg((const float4*)(bias + n_base + 4));

#pragma unroll
    for (int i = 0; i < 8; i++) {
        size_t m = mblk * 128 + tm * 8 + i;
        float* op = g_xg + m * G3 + n_base;
        float2 v0 = *(float2*)&acc[i][0];
        float2 v1 = *(float2*)&acc[i][1];
        float2 v2 = *(float2*)&acc[i][2];
        float2 v3 = *(float2*)&acc[i][3];
        float4 o0 = make_float4(v0.x + bl[0], v0.y + bl[1], v1.x + bl[2], v1.y + bl[3]);
        float4 o1 = make_float4(v2.x + bl[4], v2.y + bl[5], v3.x + bl[6], v3.y + bl[7]);
        *(float4*)op       = o0;
        *(float4*)(op + 4) = o1;
    }
}

// ===========================================================================
// Kernel 2: the GRU scan.
// 4-CTA clusters; cluster = 4 batches; CTA rank c owns hidden units
// [c*64, c*64+64). W_hh slice (192 rows x 256) in smem fp32 (padded stride).
// Per step: owner decays its h slice, DSMEM-broadcasts to all 4 replicas,
// cluster.sync, 192 threads do the (gate,unit)x(4 batch) matvec, syncthreads,
// 256 threads combine gates and keep h in registers.
// ===========================================================================
#define W_STRIDE 260
#define OFF_BH   (3 * 64 * W_STRIDE)            // 49920
#define OFF_HBUF (OFF_BH + 192)                 // 50112
#define OFF_HG   (OFF_HBUF + 2 * 4 * 256)       // 52160
#define SCAN_SMEM_FLOATS (OFF_HG + 3 * 64 * 5)  // 53120
#define SCAN_SMEM_BYTES  (SCAN_SMEM_FLOATS * 4) // 212480

__device__ __forceinline__ float sigmoidf_(float x) {
    return 1.0f / (1.0f + __expf(-x));
}

__global__ void __cluster_dims__(4, 1, 1) __launch_bounds__(256, 1)
scan_kernel(const float* __restrict__ rel_pos, const float* __restrict__ alpha,
            const float* __restrict__ W_hh, const float* __restrict__ b_hh)
{
    extern __shared__ float sm[];
    cg::cluster_group cluster = cg::this_cluster();
    const int crank = cluster.block_rank();     // 0..3
    const int cid   = blockIdx.x >> 2;          // 0..31
    const int tid   = threadIdx.x;

    float* Wsm  = sm;
    float* bh   = sm + OFF_BH;
    float* hbuf = sm + OFF_HBUF;   // [2][4][256]
    float* hg   = sm + OFF_HG;     // [3*64][5]

    // ---- load W_hh slice: rows (gate*256 + crank*64 + u), k=0..255 ----
    for (int idx = tid; idx < 192 * 64; idx += 256) {
        int row  = idx >> 6;          // 0..191 = gate*64 + u
        int c4   = idx & 63;          // 0..63  (float4 col)
        int gate = row >> 6;
        int u    = row & 63;
        float4 v = __ldg((const float4*)(W_hh +
                     (size_t)(gate * 256 + crank * 64 + u) * HH + c4 * 4));
        *(float4*)(Wsm + (size_t)row * W_STRIDE + c4 * 4) = v;
    }
    if (tid < 192) {
        int gate = tid >> 6, u = tid & 63;
        bh[tid] = b_hh[gate * 256 + crank * 64 + u];
    }
    __syncthreads();

    const int b = tid >> 6;           // 0..3 (batch within cluster)
    const int u = tid & 63;           // 0..63 (unit within slice)
    const int batch = cid * 4 + b;
    const float a = fabsf(alpha[0]);

    const float* rp = rel_pos + (size_t)batch * SS;
    const float* xg_base = g_xg + ((size_t)batch * SS) * G3 + crank * 64 + u;
    float* hs_base = g_hs + ((size_t)batch * SS) * HH + crank * 64 + u;

    float h = 0.0f;
    float rp_prev = 0.0f;
    const float* wrow = Wsm + (size_t)tid * W_STRIDE;  // valid when tid<192

    for (int t = 0; t < SS; t++) {
        const int p = t & 1;

        // ---- phase 1: decay + broadcast + xg loads ----
        float rp_t = rp[t];
        float dt = rp_t - rp_prev;
        rp_prev = rp_t;
        float hd = h * __expf(-a * dt);

        const float* xgp = xg_base + (size_t)t * G3;
        float xr = xgp[0], xz = xgp[256], xn = xgp[512];

        {
            float* lsrc = hbuf + ((p * 4 + b) * 256 + crank * 64 + u);
#pragma unroll
            for (int r = 0; r < 4; r++) {
                float* dst = (float*)cluster.map_shared_rank((void*)lsrc, r);
                *dst = hd;
            }
        }
        cluster.sync();

        // ---- phase 2: matvec hg = W_slice @ h_full + b_hh ----
        if (tid < 192) {
            float bias = bh[tid];
            float acc0 = bias, acc1 = bias, acc2 = bias, acc3 = bias;
            const float4* w4 = (const float4*)wrow;
            const float4* h0 = (const float4*)(hbuf + (p * 4 + 0) * 256);
            const float4* h1 = (const float4*)(hbuf + (p * 4 + 1) * 256);
            const float4* h2 = (const float4*)(hbuf + (p * 4 + 2) * 256);
            const float4* h3 = (const float4*)(hbuf + (p * 4 + 3) * 256);
#pragma unroll 4
            for (int kc = 0; kc < 64; kc++) {
                float4 w = w4[kc];
                float4 v;
                v = h0[kc];
                acc0 = fmaf(w.x, v.x, acc0); acc0 = fmaf(w.y, v.y, acc0);
                acc0 = fmaf(w.z, v.z, acc0); acc0 = fmaf(w.w, v.w, acc0);
                v = h1[kc];
                acc1 = fmaf(w.x, v.x, acc1); acc1 = fmaf(w.y, v.y, acc1);
                acc1 = fmaf(w.z, v.z, acc1); acc1 = fmaf(w.w, v.w, acc1);
                v = h2[kc];
                acc2 = fmaf(w.x, v.x, acc2); acc2 = fmaf(w.y, v.y, acc2);
                acc2 = fmaf(w.z, v.z, acc2); acc2 = fmaf(w.w, v.w, acc2);
                v = h3[kc];
                acc3 = fmaf(w.x, v.x, acc3); acc3 = fmaf(w.y, v.y, acc3);
                acc3 = fmaf(w.z, v.z, acc3); acc3 = fmaf(w.w, v.w, acc3);
            }
            float* hgp = hg + tid * 5;
            hgp[0] = acc0; hgp[1] = acc1; hgp[2] = acc2; hgp[3] = acc3;
        }
        __syncthreads();

        // ---- phase 3: gates (thread (b,u)) ----
        float hr = hg[(0 * 64 + u) * 5 + b];
        float hz = hg[(1 * 64 + u) * 5 + b];
        float hn = hg[(2 * 64 + u) * 5 + b];
        float r = sigmoidf_(xr + hr);
        float z = sigmoidf_(xz + hz);
        float n = tanhf(xn + r * hn);
        h = (1.0f - z) * n + z * hd;

        hs_base[(size_t)t * HH] = h;
    }
}

// ===========================================================================
// Kernel 3: out = hs @ W_fc^T + b_fc.  Warp per row, shfl reduction.
// ===========================================================================
__global__ __launch_bounds__(256) void fc_kernel(
    const float* __restrict__ W_fc, const float* __restrict__ b_fc,
    float* __restrict__ out)
{
    __shared__ float Wsm[OO * HH];
    __shared__ float bsm[OO];
    const int tid = threadIdx.x;
    for (int i = tid; i < OO * HH; i += 256) Wsm[i] = W_fc[i];
    if (tid < OO) bsm[tid] = b_fc[tid];
    __syncthreads();

    const int warp = tid >> 5, lane = tid & 31;
    const size_t m = (size_t)blockIdx.x * 8 + warp;

    const float4* hp = (const float4*)(g_hs + m * HH + lane * 8);
    float4 hv0 = hp[0], hv1 = hp[1];

    float acc[OO];
#pragma unroll
    for (int o = 0; o < OO; o++) {
        const float* w = Wsm + o * HH + lane * 8;
        float4 w0 = *(const float4*)w;
        float4 w1 = *(const float4*)(w + 4);
        float s;
        s = hv0.x * w0.x;
        s = fmaf(hv0.y, w0.y, s);
        s = fmaf(hv0.z, w0.z, s);
        s = fmaf(hv0.w, w0.w, s);
        s = fmaf(hv1.x, w1.x, s);
        s = fmaf(hv1.y, w1.y, s);
        s = fmaf(hv1.z, w1.z, s);
        s = fmaf(hv1.w, w1.w, s);
        acc[o] = s;
    }
#pragma unroll
    for (int sft = 16; sft; sft >>= 1)
#pragma unroll
        for (int o = 0; o < OO; o++)
            acc[o] += __shfl_xor_sync(0xFFFFFFFFu, acc[o], sft);

    if (lane == 0) {
#pragma unroll
        for (int o = 0; o < OO; o++)
            out[m * OO + o] = acc[o] + bsm[o];
    }
}

// ===========================================================================
// Launch
// ===========================================================================
extern "C" void kernel_launch(void* const* d_in, const int* in_sizes, int n_in,
                              void* d_out, int out_size)
{
    const float* x       = (const float*)d_in[0];
    const float* rel_pos = (const float*)d_in[1];
    const float* alpha   = (const float*)d_in[2];
    const float* W_ih    = (const float*)d_in[3];
    const float* b_ih    = (const float*)d_in[4];
    const float* W_hh    = (const float*)d_in[5];
    const float* b_hh    = (const float*)d_in[6];
    const float* W_fc    = (const float*)d_in[7];
    const float* b_fc    = (const float*)d_in[8];
    float* out = (float*)d_out;

    (void)in_sizes; (void)n_in; (void)out_size;

    // 1) Input projection
    dim3 ggrid(G3 / 128, MM / 128);   // (6, 1024)
    gemm_xg_kernel<<<ggrid, 256>>>(x, W_ih, b_ih);

    // 2) Scan (4-CTA clusters, 212.5 KB smem)
    cudaFuncSetAttribute(scan_kernel,
                         cudaFuncAttributeMaxDynamicSharedMemorySize,
                         SCAN_SMEM_BYTES);
    scan_kernel<<<128, 256, SCAN_SMEM_BYTES>>>(rel_pos, alpha, W_hh, b_hh);

    // 3) Output FC
    fc_kernel<<<MM / 8, 256>>>(W_fc, b_fc, out);
}

// round 4
// speedup vs baseline: 1.3449x; 1.3449x over previous
#include <cuda_runtime.h>
#include <cuda_bf16.h>
#include <cooperative_groups.h>
#include <cstdint>

namespace cg = cooperative_groups;

// Problem constants
#define BB 128          // batch
#define SS 1024         // seq
#define II 768          // input dim
#define HH 256          // hidden
#define OO 6            // output
#define MM (BB * SS)    // 131072 rows
#define G3 (3 * HH)     // 768 gate rows

#define KP   2304       // packed K' = 3*768 (bf16 hi|hi|lo)
#define KPB  (KP * 2)   // 4608 bytes per packed row
#define BKC  64         // K-chunk (bf16 elems) = 128 bytes
#define NCHUNK (KP / BKC)   // 36
#define NSTG 3
#define STG_BYTES 32768     // A 16KB + B 16KB

// ---------------------------------------------------------------------------
// Scratch (device globals — allocation-free rule)
// ---------------------------------------------------------------------------
__device__ __align__(128) float g_xg[(size_t)MM * G3];           // [M, 768]
__device__ __align__(128) float g_hs[(size_t)MM * HH];           // [M, 256]
__device__ __align__(128) __nv_bfloat16 g_ax[(size_t)MM * KP];   // packed A'
__device__ __align__(128) __nv_bfloat16 g_bx[(size_t)G3 * KP];   // packed B'

// ---------------------------------------------------------------------------
// Generic-PTX helpers (no sm_103a-gated instructions!)
// ---------------------------------------------------------------------------
__device__ __forceinline__ uint32_t smem_u32(const void* p) {
    uint32_t r;
    asm("{ .reg .u64 t; cvta.to.shared.u64 t, %1; cvt.u32.u64 %0, t; }"
        : "=r"(r) : "l"(p));
    return r;
}

__device__ __forceinline__ void cpa16(uint32_t saddr, const char* g) {
    asm volatile("cp.async.cg.shared.global [%0], [%1], 16;" :: "r"(saddr), "l"(g));
}

#define LDSM_X4(r, addr) \
    asm volatile("ldmatrix.sync.aligned.m8n8.x4.shared.b16 {%0,%1,%2,%3}, [%4];" \
                 : "=r"((r)[0]), "=r"((r)[1]), "=r"((r)[2]), "=r"((r)[3]) : "r"(addr))

#define MMA_16816(d, a, b0, b1) \
    asm volatile("mma.sync.aligned.m16n8k16.row.col.f32.bf16.bf16.f32 " \
                 "{%0,%1,%2,%3}, {%4,%5,%6,%7}, {%8,%9}, {%0,%1,%2,%3};" \
                 : "+f"((d)[0]), "+f"((d)[1]), "+f"((d)[2]), "+f"((d)[3]) \
                 : "r"((a)[0]), "r"((a)[1]), "r"((a)[2]), "r"((a)[3]), \
                   "r"(b0), "r"(b1))

// ===========================================================================
// Convert kernels: split fp32 -> bf16 hi/lo, pack K' = [hi | hi | lo]
// ===========================================================================
__global__ __launch_bounds__(192) void convert_x_kernel(const float* __restrict__ x)
{
    const size_t row = blockIdx.x;
    const int t = threadIdx.x;
    float4 v = __ldg((const float4*)(x + row * II) + t);
    __nv_bfloat16 h0 = __float2bfloat16_rn(v.x);
    __nv_bfloat16 h1 = __float2bfloat16_rn(v.y);
    __nv_bfloat16 h2 = __float2bfloat16_rn(v.z);
    __nv_bfloat16 h3 = __float2bfloat16_rn(v.w);
    __nv_bfloat16 l0 = __float2bfloat16_rn(v.x - __bfloat162float(h0));
    __nv_bfloat16 l1 = __float2bfloat16_rn(v.y - __bfloat162float(h1));
    __nv_bfloat16 l2 = __float2bfloat16_rn(v.z - __bfloat162float(h2));
    __nv_bfloat16 l3 = __float2bfloat16_rn(v.w - __bfloat162float(h3));
    __nv_bfloat162 hp0 = __halves2bfloat162(h0, h1);
    __nv_bfloat162 hp1 = __halves2bfloat162(h2, h3);
    __nv_bfloat162 lp0 = __halves2bfloat162(l0, l1);
    __nv_bfloat162 lp1 = __halves2bfloat162(l2, l3);
    __nv_bfloat162* base = (__nv_bfloat162*)(g_ax + row * KP);
    base[t * 2]       = hp0;  base[t * 2 + 1]       = hp1;
    base[384 + t * 2] = hp0;  base[384 + t * 2 + 1] = hp1;
    base[768 + t * 2] = lp0;  base[768 + t * 2 + 1] = lp1;
}

__global__ __launch_bounds__(192) void convert_w_kernel(const float* __restrict__ W)
{
    const size_t row = blockIdx.x;
    const int t = threadIdx.x;
    float4 v = __ldg((const float4*)(W + row * II) + t);
    __nv_bfloat16 h0 = __float2bfloat16_rn(v.x);
    __nv_bfloat16 h1 = __float2bfloat16_rn(v.y);
    __nv_bfloat16 h2 = __float2bfloat16_rn(v.z);
    __nv_bfloat16 h3 = __float2bfloat16_rn(v.w);
    __nv_bfloat16 l0 = __float2bfloat16_rn(v.x - __bfloat162float(h0));
    __nv_bfloat16 l1 = __float2bfloat16_rn(v.y - __bfloat162float(h1));
    __nv_bfloat16 l2 = __float2bfloat16_rn(v.z - __bfloat162float(h2));
    __nv_bfloat16 l3 = __float2bfloat16_rn(v.w - __bfloat162float(h3));
    __nv_bfloat162 hp0 = __halves2bfloat162(h0, h1);
    __nv_bfloat162 hp1 = __halves2bfloat162(h2, h3);
    __nv_bfloat162 lp0 = __halves2bfloat162(l0, l1);
    __nv_bfloat162 lp1 = __halves2bfloat162(l2, l3);
    // B' = [Wh | Wl | Wh] pairs with A' = [xh | xh | xl]
    __nv_bfloat162* base = (__nv_bfloat162*)(g_bx + row * KP);
    base[t * 2]       = hp0;  base[t * 2 + 1]       = hp1;
    base[384 + t * 2] = lp0;  base[384 + t * 2 + 1] = lp1;
    base[768 + t * 2] = hp0;  base[768 + t * 2 + 1] = hp1;
}

// ===========================================================================
// Kernel 1: xg = x @ W_ih^T + b_ih  via mma.sync bf16 (fp32 accum)
// CTA 128x128, 8 warps (2x4), warp tile 64x32, BK=64, 3-stage cp.async.
// SW128 swizzle: seg' = seg ^ (row & 7)  (16B segments, 128B rows)
// ===========================================================================
__global__ __launch_bounds__(256, 1) void gemm_mma_kernel(
    const float* __restrict__ bias)
{
    extern __shared__ __align__(1024) char dsm[];
    __shared__ float s_bias[128];

    const int tid  = threadIdx.x;
    const int lane = tid & 31;
    const int warp = tid >> 5;
    const int wm = warp >> 2;         // 0..1
    const int wn = warp & 3;          // 0..3
    const int n0 = blockIdx.x * 128;  // 0..640
    const size_t m0 = (size_t)blockIdx.y * 128;

    const uint32_t smem_base = smem_u32(dsm);

    if (tid < 128) s_bias[tid] = __ldg(bias + n0 + tid);

    const char* gA = (const char*)(g_ax) + m0 * KPB;
    const char* gB = (const char*)(g_bx) + (size_t)n0 * KPB;

    // per-chunk loads: 1024 segs A + 1024 segs B over 256 threads
    auto issue_loads = [&](int slot, int kbyte) {
        const uint32_t stgA = smem_base + slot * STG_BYTES;
        const uint32_t stgB = stgA + 16384;
#pragma unroll
        for (int i = 0; i < 4; i++) {
            int seg = tid + i * 256;            // 0..1023
            int r = seg >> 3, c = seg & 7;
            uint32_t off = (uint32_t)(r * 128 + ((c ^ (r & 7)) << 4));
            const size_t goff = (size_t)r * KPB + kbyte + c * 16;
            cpa16(stgA + off, gA + goff);
            cpa16(stgB + off, gB + goff);
        }
    };

    // ldmatrix lane address components
    const int lrow = (lane & 7) + ((lane >> 3) & 1) * 8;   // 0..15
    const int cp   = lane >> 4;                            // 0,1 (k half)
    const int arow = wm * 64 + lrow;
    const int brow = wn * 32 + lrow;

    float acc[4][4][4];
#pragma unroll
    for (int f = 0; f < 4; f++)
#pragma unroll
        for (int g = 0; g < 4; g++)
#pragma unroll
            for (int r = 0; r < 4; r++) acc[f][g][r] = 0.0f;

    // Prologue: chunks 0,1 -> slots 0,1
    issue_loads(0, 0);
    asm volatile("cp.async.commit_group;" ::: "memory");
    issue_loads(1, 128);
    asm volatile("cp.async.commit_group;" ::: "memory");

    for (int c = 0; c < NCHUNK; c++) {
        const int lc = c + 2;
        if (lc < NCHUNK) issue_loads(lc % NSTG, lc * 128);
        asm volatile("cp.async.commit_group;" ::: "memory");
        asm volatile("cp.async.wait_group 2;" ::: "memory");
        __syncthreads();

        const uint32_t stgA = smem_base + (c % NSTG) * STG_BYTES;
        const uint32_t stgB = stgA + 16384;

#pragma unroll
        for (int s = 0; s < 4; s++) {           // 4 k-steps of 16
            const int ach = ((2 * s + cp) ^ (arow & 7)) << 4;
            const int bch = ((2 * s + cp) ^ (brow & 7)) << 4;
            uint32_t a[4][4];
            uint32_t b[2][4];
#pragma unroll
            for (int f = 0; f < 4; f++)
                LDSM_X4(a[f], stgA + (uint32_t)((arow + f * 16) * 128 + ach));
#pragma unroll
            for (int g2 = 0; g2 < 2; g2++)
                LDSM_X4(b[g2], stgB + (uint32_t)((brow + g2 * 16) * 128 + bch));
#pragma unroll
            for (int f = 0; f < 4; f++) {
#pragma unroll
                for (int g = 0; g < 4; g++)
                    MMA_16816(acc[f][g], a[f], b[g >> 1][g & 1], b[g >> 1][(g & 1) + 2]);
            }
        }
        __syncthreads();
    }

    // Epilogue: add bias, store fp32
    const int qrow = lane >> 2;          // 0..7
    const int qcol = (lane & 3) * 2;     // 0,2,4,6
#pragma unroll
    for (int f = 0; f < 4; f++) {
        const size_t gr = m0 + wm * 64 + f * 16 + qrow;
#pragma unroll
        for (int g = 0; g < 4; g++) {
            const int lc = wn * 32 + g * 8 + qcol;
            const float b0 = s_bias[lc], b1 = s_bias[lc + 1];
            float* p0 = g_xg + gr * G3 + n0 + lc;
            float* p1 = p0 + 8 * G3;
            *(float2*)p0 = make_float2(acc[f][g][0] + b0, acc[f][g][1] + b1);
            *(float2*)p1 = make_float2(acc[f][g][2] + b0, acc[f][g][3] + b1);
        }
    }
}

// ===========================================================================
// Kernel 2: the GRU scan (4-CTA clusters, DSMEM) — unchanged (known good).
// ===========================================================================
#define W_STRIDE 260
#define OFF_BH   (3 * 64 * W_STRIDE)
#define OFF_HBUF (OFF_BH + 192)
#define OFF_HG   (OFF_HBUF + 2 * 4 * 256)
#define SCAN_SMEM_FLOATS (OFF_HG + 3 * 64 * 5)
#define SCAN_SMEM_BYTES  (SCAN_SMEM_FLOATS * 4)

__device__ __forceinline__ float sigmoidf_(float x) {
    return 1.0f / (1.0f + __expf(-x));
}

__global__ void __cluster_dims__(4, 1, 1) __launch_bounds__(256, 1)
scan_kernel(const float* __restrict__ rel_pos, const float* __restrict__ alpha,
            const float* __restrict__ W_hh, const float* __restrict__ b_hh)
{
    extern __shared__ float sm[];
    cg::cluster_group cluster = cg::this_cluster();
    const int crank = cluster.block_rank();
    const int cid   = blockIdx.x >> 2;
    const int tid   = threadIdx.x;

    float* Wsm  = sm;
    float* bh   = sm + OFF_BH;
    float* hbuf = sm + OFF_HBUF;
    float* hg   = sm + OFF_HG;

    for (int idx = tid; idx < 192 * 64; idx += 256) {
        int row  = idx >> 6;
        int c4   = idx & 63;
        int gate = row >> 6;
        int u    = row & 63;
        float4 v = __ldg((const float4*)(W_hh +
                     (size_t)(gate * 256 + crank * 64 + u) * HH + c4 * 4));
        *(float4*)(Wsm + (size_t)row * W_STRIDE + c4 * 4) = v;
    }
    if (tid < 192) {
        int gate = tid >> 6, u = tid & 63;
        bh[tid] = b_hh[gate * 256 + crank * 64 + u];
    }
    __syncthreads();

    const int b = tid >> 6;
    const int u = tid & 63;
    const int batch = cid * 4 + b;
    const float a = fabsf(alpha[0]);

    const float* rp = rel_pos + (size_t)batch * SS;
    const float* xg_base = g_xg + ((size_t)batch * SS) * G3 + crank * 64 + u;
    float* hs_base = g_hs + ((size_t)batch * SS) * HH + crank * 64 + u;

    float h = 0.0f;
    float rp_prev = 0.0f;
    const float* wrow = Wsm + (size_t)tid * W_STRIDE;

    for (int t = 0; t < SS; t++) {
        const int p = t & 1;

        float rp_t = rp[t];
        float dt = rp_t - rp_prev;
        rp_prev = rp_t;
        float hd = h * __expf(-a * dt);

        const float* xgp = xg_base + (size_t)t * G3;
        float xr = xgp[0], xz = xgp[256], xn = xgp[512];

        {
            float* lsrc = hbuf + ((p * 4 + b) * 256 + crank * 64 + u);
#pragma unroll
            for (int r = 0; r < 4; r++) {
                float* dst = (float*)cluster.map_shared_rank((void*)lsrc, r);
                *dst = hd;
            }
        }
        cluster.sync();

        if (tid < 192) {
            float bias = bh[tid];
            float acc0 = bias, acc1 = bias, acc2 = bias, acc3 = bias;
            const float4* w4 = (const float4*)wrow;
            const float4* h0 = (const float4*)(hbuf + (p * 4 + 0) * 256);
            const float4* h1 = (const float4*)(hbuf + (p * 4 + 1) * 256);
            const float4* h2 = (const float4*)(hbuf + (p * 4 + 2) * 256);
            const float4* h3 = (const float4*)(hbuf + (p * 4 + 3) * 256);
#pragma unroll 4
            for (int kc = 0; kc < 64; kc++) {
                float4 w = w4[kc];
                float4 v;
                v = h0[kc];
                acc0 = fmaf(w.x, v.x, acc0); acc0 = fmaf(w.y, v.y, acc0);
                acc0 = fmaf(w.z, v.z, acc0); acc0 = fmaf(w.w, v.w, acc0);
                v = h1[kc];
                acc1 = fmaf(w.x, v.x, acc1); acc1 = fmaf(w.y, v.y, acc1);
                acc1 = fmaf(w.z, v.z, acc1); acc1 = fmaf(w.w, v.w, acc1);
                v = h2[kc];
                acc2 = fmaf(w.x, v.x, acc2); acc2 = fmaf(w.y, v.y, acc2);
                acc2 = fmaf(w.z, v.z, acc2); acc2 = fmaf(w.w, v.w, acc2);
                v = h3[kc];
                acc3 = fmaf(w.x, v.x, acc3); acc3 = fmaf(w.y, v.y, acc3);
                acc3 = fmaf(w.z, v.z, acc3); acc3 = fmaf(w.w, v.w, acc3);
            }
            float* hgp = hg + tid * 5;
            hgp[0] = acc0; hgp[1] = acc1; hgp[2] = acc2; hgp[3] = acc3;
        }
        __syncthreads();

        float hr = hg[(0 * 64 + u) * 5 + b];
        float hz = hg[(1 * 64 + u) * 5 + b];
        float hn = hg[(2 * 64 + u) * 5 + b];
        float r = sigmoidf_(xr + hr);
        float z = sigmoidf_(xz + hz);
        float n = tanhf(xn + r * hn);
        h = (1.0f - z) * n + z * hd;

        hs_base[(size_t)t * HH] = h;
    }
}

// ===========================================================================
// Kernel 3: out = hs @ W_fc^T + b_fc.
// ===========================================================================
__global__ __launch_bounds__(256) void fc_kernel(
    const float* __restrict__ W_fc, const float* __restrict__ b_fc,
    float* __restrict__ out)
{
    __shared__ float Wsm[OO * HH];
    __shared__ float bsm[OO];
    const int tid = threadIdx.x;
    for (int i = tid; i < OO * HH; i += 256) Wsm[i] = W_fc[i];
    if (tid < OO) bsm[tid] = b_fc[tid];
    __syncthreads();

    const int warp = tid >> 5, lane = tid & 31;
    const size_t m = (size_t)blockIdx.x * 8 + warp;

    const float4* hp = (const float4*)(g_hs + m * HH + lane * 8);
    float4 hv0 = hp[0], hv1 = hp[1];

    float acc[OO];
#pragma unroll
    for (int o = 0; o < OO; o++) {
        const float* w = Wsm + o * HH + lane * 8;
        float4 w0 = *(const float4*)w;
        float4 w1 = *(const float4*)(w + 4);
        float s;
        s = hv0.x * w0.x;
        s = fmaf(hv0.y, w0.y, s);
        s = fmaf(hv0.z, w0.z, s);
        s = fmaf(hv0.w, w0.w, s);
        s = fmaf(hv1.x, w1.x, s);
        s = fmaf(hv1.y, w1.y, s);
        s = fmaf(hv1.z, w1.z, s);
        s = fmaf(hv1.w, w1.w, s);
        acc[o] = s;
    }
#pragma unroll
    for (int sft = 16; sft; sft >>= 1)
#pragma unroll
        for (int o = 0; o < OO; o++)
            acc[o] += __shfl_xor_sync(0xFFFFFFFFu, acc[o], sft);

    if (lane == 0) {
#pragma unroll
        for (int o = 0; o < OO; o++)
            out[m * OO + o] = acc[o] + bsm[o];
    }
}

// ===========================================================================
// Launch
// ===========================================================================
extern "C" void kernel_launch(void* const* d_in, const int* in_sizes, int n_in,
                              void* d_out, int out_size)
{
    const float* x       = (const float*)d_in[0];
    const float* rel_pos = (const float*)d_in[1];
    const float* alpha   = (const float*)d_in[2];
    const float* W_ih    = (const float*)d_in[3];
    const float* b_ih    = (const float*)d_in[4];
    const float* W_hh    = (const float*)d_in[5];
    const float* b_hh    = (const float*)d_in[6];
    const float* W_fc    = (const float*)d_in[7];
    const float* b_fc    = (const float*)d_in[8];
    float* out = (float*)d_out;

    (void)in_sizes; (void)n_in; (void)out_size;

    // 0) bf16 hi/lo packing
    convert_x_kernel<<<MM, 192>>>(x);
    convert_w_kernel<<<G3, 192>>>(W_ih);

    // 1) Input projection via mma.sync (6 n-tiles x 1024 m-tiles)
    cudaFuncSetAttribute(gemm_mma_kernel,
                         cudaFuncAttributeMaxDynamicSharedMemorySize,
                         NSTG * STG_BYTES);
    dim3 ggrid(6, 1024);
    gemm_mma_kernel<<<ggrid, 256, NSTG * STG_BYTES>>>(b_ih);

    // 2) Scan (4-CTA clusters)
    cudaFuncSetAttribute(scan_kernel,
                         cudaFuncAttributeMaxDynamicSharedMemorySize,
                         SCAN_SMEM_BYTES);
    scan_kernel<<<128, 256, SCAN_SMEM_BYTES>>>(rel_pos, alpha, W_hh, b_hh);

    // 3) Output FC
    fc_kernel<<<MM / 8, 256>>>(W_fc, b_fc, out);
}

// round 5
// speedup vs baseline: 1.4615x; 1.0867x over previous
#include <cuda_runtime.h>
#include <cuda_bf16.h>
#include <cooperative_groups.h>
#include <cstdint>

namespace cg = cooperative_groups;

// Problem constants
#define BB 128          // batch
#define SS 1024         // seq
#define II 768          // input dim
#define HH 256          // hidden
#define OO 6            // output
#define MM (BB * SS)    // 131072 rows
#define G3 (3 * HH)     // 768 gate rows

#define KP   2304       // packed K' = 3*768 (bf16 hi|hi|lo)
#define KPB  (KP * 2)   // 4608 bytes per packed row
#define BKC  64         // K-chunk (bf16 elems) = 128 bytes
#define NCHUNK (KP / BKC)   // 36
#define NSTG 3
#define STG_BYTES 32768     // A 16KB + B 16KB

typedef unsigned long long ull;

// ---------------------------------------------------------------------------
// Scratch (device globals — allocation-free rule)
// ---------------------------------------------------------------------------
__device__ __align__(128) float g_xg[(size_t)MM * G3];           // [M, 768]
__device__ __align__(128) float g_hs[(size_t)MM * HH];           // [M, 256]
__device__ __align__(128) __nv_bfloat16 g_ax[(size_t)MM * KP];   // packed A'
__device__ __align__(128) __nv_bfloat16 g_bx[(size_t)G3 * KP];   // packed B'

// ---------------------------------------------------------------------------
// Generic-PTX helpers (no sm_103a-gated instructions!)
// ---------------------------------------------------------------------------
__device__ __forceinline__ uint32_t smem_u32(const void* p) {
    uint32_t r;
    asm("{ .reg .u64 t; cvta.to.shared.u64 t, %1; cvt.u32.u64 %0, t; }"
        : "=r"(r) : "l"(p));
    return r;
}

__device__ __forceinline__ void cpa16(uint32_t saddr, const char* g) {
    asm volatile("cp.async.cg.shared.global [%0], [%1], 16;" :: "r"(saddr), "l"(g));
}

#define LDSM_X4(r, addr) \
    asm volatile("ldmatrix.sync.aligned.m8n8.x4.shared.b16 {%0,%1,%2,%3}, [%4];" \
                 : "=r"((r)[0]), "=r"((r)[1]), "=r"((r)[2]), "=r"((r)[3]) : "r"(addr))

#define MMA_16816(d, a, b0, b1) \
    asm volatile("mma.sync.aligned.m16n8k16.row.col.f32.bf16.bf16.f32 " \
                 "{%0,%1,%2,%3}, {%4,%5,%6,%7}, {%8,%9}, {%0,%1,%2,%3};" \
                 : "+f"((d)[0]), "+f"((d)[1]), "+f"((d)[2]), "+f"((d)[3]) \
                 : "r"((a)[0]), "r"((a)[1]), "r"((a)[2]), "r"((a)[3]), \
                   "r"(b0), "r"(b1))

#define FMA2(acc, a, b) \
    asm("fma.rn.f32x2 %0, %1, %2, %0;" : "+l"(acc) : "l"(a), "l"(b))

// ===========================================================================
// Convert kernels: split fp32 -> bf16 hi/lo, pack K' = [hi | hi | lo]
// ===========================================================================
__global__ __launch_bounds__(192) void convert_x_kernel(const float* __restrict__ x)
{
    const size_t row = blockIdx.x;
    const int t = threadIdx.x;
    float4 v = __ldg((const float4*)(x + row * II) + t);
    __nv_bfloat16 h0 = __float2bfloat16_rn(v.x);
    __nv_bfloat16 h1 = __float2bfloat16_rn(v.y);
    __nv_bfloat16 h2 = __float2bfloat16_rn(v.z);
    __nv_bfloat16 h3 = __float2bfloat16_rn(v.w);
    __nv_bfloat16 l0 = __float2bfloat16_rn(v.x - __bfloat162float(h0));
    __nv_bfloat16 l1 = __float2bfloat16_rn(v.y - __bfloat162float(h1));
    __nv_bfloat16 l2 = __float2bfloat16_rn(v.z - __bfloat162float(h2));
    __nv_bfloat16 l3 = __float2bfloat16_rn(v.w - __bfloat162float(h3));
    __nv_bfloat162 hp0 = __halves2bfloat162(h0, h1);
    __nv_bfloat162 hp1 = __halves2bfloat162(h2, h3);
    __nv_bfloat162 lp0 = __halves2bfloat162(l0, l1);
    __nv_bfloat162 lp1 = __halves2bfloat162(l2, l3);
    __nv_bfloat162* base = (__nv_bfloat162*)(g_ax + row * KP);
    base[t * 2]       = hp0;  base[t * 2 + 1]       = hp1;
    base[384 + t * 2] = hp0;  base[384 + t * 2 + 1] = hp1;
    base[768 + t * 2] = lp0;  base[768 + t * 2 + 1] = lp1;
}

__global__ __launch_bounds__(192) void convert_w_kernel(const float* __restrict__ W)
{
    const size_t row = blockIdx.x;
    const int t = threadIdx.x;
    float4 v = __ldg((const float4*)(W + row * II) + t);
    __nv_bfloat16 h0 = __float2bfloat16_rn(v.x);
    __nv_bfloat16 h1 = __float2bfloat16_rn(v.y);
    __nv_bfloat16 h2 = __float2bfloat16_rn(v.z);
    __nv_bfloat16 h3 = __float2bfloat16_rn(v.w);
    __nv_bfloat16 l0 = __float2bfloat16_rn(v.x - __bfloat162float(h0));
    __nv_bfloat16 l1 = __float2bfloat16_rn(v.y - __bfloat162float(h1));
    __nv_bfloat16 l2 = __float2bfloat16_rn(v.z - __bfloat162float(h2));
    __nv_bfloat16 l3 = __float2bfloat16_rn(v.w - __bfloat162float(h3));
    __nv_bfloat162 hp0 = __halves2bfloat162(h0, h1);
    __nv_bfloat162 hp1 = __halves2bfloat162(h2, h3);
    __nv_bfloat162 lp0 = __halves2bfloat162(l0, l1);
    __nv_bfloat162 lp1 = __halves2bfloat162(l2, l3);
    // B' = [Wh | Wl | Wh] pairs with A' = [xh | xh | xl]
    __nv_bfloat162* base = (__nv_bfloat162*)(g_bx + row * KP);
    base[t * 2]       = hp0;  base[t * 2 + 1]       = hp1;
    base[384 + t * 2] = lp0;  base[384 + t * 2 + 1] = lp1;
    base[768 + t * 2] = hp0;  base[768 + t * 2 + 1] = hp1;
}

// ===========================================================================
// Kernel 1: xg = x @ W_ih^T + b_ih  via mma.sync bf16 (fp32 accum)
// (unchanged from round 4 — known good)
// ===========================================================================
__global__ __launch_bounds__(256, 1) void gemm_mma_kernel(
    const float* __restrict__ bias)
{
    extern __shared__ __align__(1024) char dsm[];
    __shared__ float s_bias[128];

    const int tid  = threadIdx.x;
    const int lane = tid & 31;
    const int warp = tid >> 5;
    const int wm = warp >> 2;
    const int wn = warp & 3;
    const int n0 = blockIdx.x * 128;
    const size_t m0 = (size_t)blockIdx.y * 128;

    const uint32_t smem_base = smem_u32(dsm);

    if (tid < 128) s_bias[tid] = __ldg(bias + n0 + tid);

    const char* gA = (const char*)(g_ax) + m0 * KPB;
    const char* gB = (const char*)(g_bx) + (size_t)n0 * KPB;

    auto issue_loads = [&](int slot, int kbyte) {
        const uint32_t stgA = smem_base + slot * STG_BYTES;
        const uint32_t stgB = stgA + 16384;
#pragma unroll
        for (int i = 0; i < 4; i++) {
            int seg = tid + i * 256;
            int r = seg >> 3, c = seg & 7;
            uint32_t off = (uint32_t)(r * 128 + ((c ^ (r & 7)) << 4));
            const size_t goff = (size_t)r * KPB + kbyte + c * 16;
            cpa16(stgA + off, gA + goff);
            cpa16(stgB + off, gB + goff);
        }
    };

    const int lrow = (lane & 7) + ((lane >> 3) & 1) * 8;
    const int cp   = lane >> 4;
    const int arow = wm * 64 + lrow;
    const int brow = wn * 32 + lrow;

    float acc[4][4][4];
#pragma unroll
    for (int f = 0; f < 4; f++)
#pragma unroll
        for (int g = 0; g < 4; g++)
#pragma unroll
            for (int r = 0; r < 4; r++) acc[f][g][r] = 0.0f;

    issue_loads(0, 0);
    asm volatile("cp.async.commit_group;" ::: "memory");
    issue_loads(1, 128);
    asm volatile("cp.async.commit_group;" ::: "memory");

    for (int c = 0; c < NCHUNK; c++) {
        const int lc = c + 2;
        if (lc < NCHUNK) issue_loads(lc % NSTG, lc * 128);
        asm volatile("cp.async.commit_group;" ::: "memory");
        asm volatile("cp.async.wait_group 2;" ::: "memory");
        __syncthreads();

        const uint32_t stgA = smem_base + (c % NSTG) * STG_BYTES;
        const uint32_t stgB = stgA + 16384;

#pragma unroll
        for (int s = 0; s < 4; s++) {
            const int ach = ((2 * s + cp) ^ (arow & 7)) << 4;
            const int bch = ((2 * s + cp) ^ (brow & 7)) << 4;
            uint32_t a[4][4];
            uint32_t b[2][4];
#pragma unroll
            for (int f = 0; f < 4; f++)
                LDSM_X4(a[f], stgA + (uint32_t)((arow + f * 16) * 128 + ach));
#pragma unroll
            for (int g2 = 0; g2 < 2; g2++)
                LDSM_X4(b[g2], stgB + (uint32_t)((brow + g2 * 16) * 128 + bch));
#pragma unroll
            for (int f = 0; f < 4; f++) {
#pragma unroll
                for (int g = 0; g < 4; g++)
                    MMA_16816(acc[f][g], a[f], b[g >> 1][g & 1], b[g >> 1][(g & 1) + 2]);
            }
        }
        __syncthreads();
    }

    const int qrow = lane >> 2;
    const int qcol = (lane & 3) * 2;
#pragma unroll
    for (int f = 0; f < 4; f++) {
        const size_t gr = m0 + wm * 64 + f * 16 + qrow;
#pragma unroll
        for (int g = 0; g < 4; g++) {
            const int lc = wn * 32 + g * 8 + qcol;
            const float b0 = s_bias[lc], b1 = s_bias[lc + 1];
            float* p0 = g_xg + gr * G3 + n0 + lc;
            float* p1 = p0 + 8 * G3;
            *(float2*)p0 = make_float2(acc[f][g][0] + b0, acc[f][g][1] + b1);
            *(float2*)p1 = make_float2(acc[f][g][2] + b0, acc[f][g][3] + b1);
        }
    }
}

// ===========================================================================
// Kernel 2: the GRU scan — REBUILT.
// 4-CTA cluster = 4 batches; CTA rank c owns hidden units [c*64, c*64+64).
// Thread (u = tid>>2, b = tid&3) computes ALL 3 gate dot-products for its
// (batch b, unit u) with f32x2 FMAs, then the gate math in registers.
// One split cluster barrier per step; xg/rel_pos prefetched into the
// arrive->wait gap. Weights in smem (192 rows x 256, stride 260, fp32).
// ===========================================================================
#define WS 260
#define OFF_HBUF (192 * WS)                    // 49920 floats
#define SCAN_SMEM_FLOATS (OFF_HBUF + 2 * 4 * WS)   // 52000
#define SCAN_SMEM_BYTES  (SCAN_SMEM_FLOATS * 4)    // 208000

__device__ __forceinline__ float fast_sig(float x) {
    float xc = fminf(fmaxf(x, -80.f), 80.f);
    return __fdividef(1.f, 1.f + __expf(-xc));
}
__device__ __forceinline__ float fast_tanh(float x) {
    float xc = fminf(fmaxf(x, -40.f), 40.f);
    return 1.f - __fdividef(2.f, __expf(2.f * xc) + 1.f);
}

__global__ void __cluster_dims__(4, 1, 1) __launch_bounds__(256, 1)
scan_kernel(const float* __restrict__ rel_pos, const float* __restrict__ alpha,
            const float* __restrict__ W_hh, const float* __restrict__ b_hh)
{
    extern __shared__ float sm[];
    cg::cluster_group cluster = cg::this_cluster();
    const int crank = cluster.block_rank();     // 0..3
    const int cid   = blockIdx.x >> 2;          // 0..31
    const int tid   = threadIdx.x;
    const int u = tid >> 2;                     // 0..63
    const int b = tid & 3;                      // 0..3

    float* hbuf = sm + OFF_HBUF;                // [2][4][WS]

    // ---- load W_hh slice: dst row = gate*64 + uu, k = 0..255 ----
    for (int idx = tid; idx < 192 * 64; idx += 256) {
        int row = idx >> 6;            // 0..191
        int c4  = idx & 63;
        int g   = row >> 6;
        int uu  = row & 63;
        float4 v = __ldg((const float4*)(W_hh +
                     (size_t)(g * 256 + crank * 64 + uu) * HH + c4 * 4));
        *(float4*)(sm + (size_t)row * WS + c4 * 4) = v;
    }

    const float bias_r = __ldg(b_hh + 0 * 256 + crank * 64 + u);
    const float bias_z = __ldg(b_hh + 1 * 256 + crank * 64 + u);
    const float bias_n = __ldg(b_hh + 2 * 256 + crank * 64 + u);
    __syncthreads();

    const int batch = cid * 4 + b;
    const float a = fabsf(__ldg(alpha));

    const float* rp = rel_pos + (size_t)batch * SS;
    const float* xg_base = g_xg + ((size_t)batch * SS) * G3 + crank * 64 + u;
    float* hs_base = g_hs + ((size_t)batch * SS) * HH + crank * 64 + u;

    // precompute the 4 remote store addresses (parity handled by offset)
    float* rdst[4];
    {
        float* lsrc = hbuf + b * WS + crank * 64 + u;
#pragma unroll
        for (int r = 0; r < 4; r++)
            rdst[r] = (float*)cluster.map_shared_rank((void*)lsrc, r);
    }

    const ulonglong2* wr = (const ulonglong2*)(sm + (size_t)(0 * 64 + u) * WS);
    const ulonglong2* wz = (const ulonglong2*)(sm + (size_t)(1 * 64 + u) * WS);
    const ulonglong2* wn = (const ulonglong2*)(sm + (size_t)(2 * 64 + u) * WS);

    // prefetch t = 0
    float rpt = __ldg(rp);
    float xr = __ldg(xg_base), xz = __ldg(xg_base + 256), xn = __ldg(xg_base + 512);

    float h = 0.0f, rp_prev = 0.0f;

    for (int t = 0; t < SS; t++) {
        const int poff = (t & 1) * (4 * WS);

        // decay + DSMEM broadcast of h
        float dt = rpt - rp_prev;
        rp_prev = rpt;
        float hd = h * __expf(-a * dt);
        rdst[0][poff] = hd;
        rdst[1][poff] = hd;
        rdst[2][poff] = hd;
        rdst[3][poff] = hd;
        asm volatile("barrier.cluster.arrive.aligned;" ::: "memory");

        // prefetch next step's xg / rel_pos into the arrive->wait gap
        const int tn = (t + 1 < SS) ? (t + 1) : (SS - 1);
        const float* xgn = xg_base + (size_t)tn * G3;
        float xr_n = __ldg(xgn), xz_n = __ldg(xgn + 256), xn_n = __ldg(xgn + 512);
        float rpt_n = __ldg(rp + tn);

        asm volatile("barrier.cluster.wait.aligned;" ::: "memory");

        // matvec: 3 gate dots over k=256, f32x2
        const ulonglong2* hb = (const ulonglong2*)(hbuf + poff + b * WS);
        ull ar = 0ull, az = 0ull, an = 0ull;
#pragma unroll 8
        for (int kc = 0; kc < 64; kc++) {
            ulonglong2 hv = hb[kc];
            ulonglong2 w0 = wr[kc];
            ulonglong2 w1 = wz[kc];
            ulonglong2 w2 = wn[kc];
            FMA2(ar, w0.x, hv.x); FMA2(ar, w0.y, hv.y);
            FMA2(az, w1.x, hv.x); FMA2(az, w1.y, hv.y);
            FMA2(an, w2.x, hv.x); FMA2(an, w2.y, hv.y);
        }
        float2 fr = *(float2*)&ar;
        float2 fz = *(float2*)&az;
        float2 fn = *(float2*)&an;
        float hr = fr.x + fr.y + bias_r;
        float hz = fz.x + fz.y + bias_z;
        float hn = fn.x + fn.y + bias_n;

        float r = fast_sig(xr + hr);
        float z = fast_sig(xz + hz);
        float n = fast_tanh(xn + r * hn);
        h = n + z * (hd - n);

        hs_base[(size_t)t * HH] = h;

        xr = xr_n; xz = xz_n; xn = xn_n; rpt = rpt_n;
    }
}

// ===========================================================================
// Kernel 3: out = hs @ W_fc^T + b_fc.
// ===========================================================================
__global__ __launch_bounds__(256) void fc_kernel(
    const float* __restrict__ W_fc, const float* __restrict__ b_fc,
    float* __restrict__ out)
{
    __shared__ float Wsm[OO * HH];
    __shared__ float bsm[OO];
    const int tid = threadIdx.x;
    for (int i = tid; i < OO * HH; i += 256) Wsm[i] = W_fc[i];
    if (tid < OO) bsm[tid] = b_fc[tid];
    __syncthreads();

    const int warp = tid >> 5, lane = tid & 31;
    const size_t m = (size_t)blockIdx.x * 8 + warp;

    const float4* hp = (const float4*)(g_hs + m * HH + lane * 8);
    float4 hv0 = hp[0], hv1 = hp[1];

    float acc[OO];
#pragma unroll
    for (int o = 0; o < OO; o++) {
        const float* w = Wsm + o * HH + lane * 8;
        float4 w0 = *(const float4*)w;
        float4 w1 = *(const float4*)(w + 4);
        float s;
        s = hv0.x * w0.x;
        s = fmaf(hv0.y, w0.y, s);
        s = fmaf(hv0.z, w0.z, s);
        s = fmaf(hv0.w, w0.w, s);
        s = fmaf(hv1.x, w1.x, s);
        s = fmaf(hv1.y, w1.y, s);
        s = fmaf(hv1.z, w1.z, s);
        s = fmaf(hv1.w, w1.w, s);
        acc[o] = s;
    }
#pragma unroll
    for (int sft = 16; sft; sft >>= 1)
#pragma unroll
        for (int o = 0; o < OO; o++)
            acc[o] += __shfl_xor_sync(0xFFFFFFFFu, acc[o], sft);

    if (lane == 0) {
#pragma unroll
        for (int o = 0; o < OO; o++)
            out[m * OO + o] = acc[o] + bsm[o];
    }
}

// ===========================================================================
// Launch
// ===========================================================================
extern "C" void kernel_launch(void* const* d_in, const int* in_sizes, int n_in,
                              void* d_out, int out_size)
{
    const float* x       = (const float*)d_in[0];
    const float* rel_pos = (const float*)d_in[1];
    const float* alpha   = (const float*)d_in[2];
    const float* W_ih    = (const float*)d_in[3];
    const float* b_ih    = (const float*)d_in[4];
    const float* W_hh    = (const float*)d_in[5];
    const float* b_hh    = (const float*)d_in[6];
    const float* W_fc    = (const float*)d_in[7];
    const float* b_fc    = (const float*)d_in[8];
    float* out = (float*)d_out;

    (void)in_sizes; (void)n_in; (void)out_size;

    // 0) bf16 hi/lo packing
    convert_x_kernel<<<MM, 192>>>(x);
    convert_w_kernel<<<G3, 192>>>(W_ih);

    // 1) Input projection via mma.sync
    cudaFuncSetAttribute(gemm_mma_kernel,
                         cudaFuncAttributeMaxDynamicSharedMemorySize,
                         NSTG * STG_BYTES);
    dim3 ggrid(6, 1024);
    gemm_mma_kernel<<<ggrid, 256, NSTG * STG_BYTES>>>(b_ih);

    // 2) Scan (4-CTA clusters, 208 KB smem)
    cudaFuncSetAttribute(scan_kernel,
                         cudaFuncAttributeMaxDynamicSharedMemorySize,
                         SCAN_SMEM_BYTES);
    scan_kernel<<<128, 256, SCAN_SMEM_BYTES>>>(rel_pos, alpha, W_hh, b_hh);

    // 3) Output FC
    fc_kernel<<<MM / 8, 256>>>(W_fc, b_fc, out);
}